// round 13
// baseline (speedup 1.0000x reference)
#include <cuda_runtime.h>
#include <math.h>
#include <stdint.h>

#define DIM      768
#define HEADS    12
#define HD       64
#define HIDDEN   3072
#define SEQ      577
#define BATCH    64
#define NTOK     (BATCH*SEQ)  // 36928
#define QKVD     (3*DIM)      // 2304

// ---------------- single scratch arena (overlaid buffers) ----------------
#define ARENA_FLOATS ((size_t)NTOK * DIM * 2 + (size_t)NTOK * HIDDEN)
__device__ __align__(16) float g_arena[ARENA_FLOATS];

// ---------------- helpers ----------------
__device__ __forceinline__ uint32_t smem_u32(const void* p) {
    uint32_t a;
    asm("{ .reg .u64 t; cvta.to.shared.u64 t, %1; cvt.u32.u64 %0, t; }"
        : "=r"(a) : "l"(p));
    return a;
}
// pack (hi,lo) floats -> bf16x2 word, RNE (one HW instruction)
__device__ __forceinline__ uint32_t cvt_bf16x2(float hi, float lo) {
    uint32_t r;
    asm("cvt.rn.bf16x2.f32 %0, %1, %2;" : "=r"(r) : "f"(hi), "f"(lo));
    return r;
}

#define LDSM4(r0, r1, r2, r3, addr) \
    asm volatile("ldmatrix.sync.aligned.m8n8.x4.shared.b16 {%0,%1,%2,%3}, [%4];" \
                 : "=r"(r0), "=r"(r1), "=r"(r2), "=r"(r3) : "r"(addr))

#define MMA_BF16(d, a, b) \
    asm volatile("mma.sync.aligned.m16n8k16.row.col.f32.bf16.bf16.f32 " \
                 "{%0,%1,%2,%3}, {%4,%5,%6,%7}, {%8,%9}, {%0,%1,%2,%3};" \
                 : "+f"((d)[0]), "+f"((d)[1]), "+f"((d)[2]), "+f"((d)[3]) \
                 : "r"((a)[0]), "r"((a)[1]), "r"((a)[2]), "r"((a)[3]), \
                   "r"((b)[0]), "r"((b)[1]))

// ============ bf16-split tensor-core GEMM: 128x256 tile, K-block 32 ==========
// A [M,K] rm, B [K,N] rm, C [M,N]. K%32==0, N%256==0.
// Each fp32 a = ah+al; smem holds K expanded 3x:
//   A slots per k: [ah, ah, al]   B slots per k: [bh, bl, bh]
// 8 warps in 2x4 grid, 64x64 per warp. Pack of next k-block is interleaved
// into the MMA chunk loop (chunks 2..5) to keep the tensor pipe fed.
#define PITCHB   208                    // bytes per smem row (104 bf16)
#define ATILE    (128 * PITCHB)         // 26624
#define BTILE    (256 * PITCHB)         // 53248
#define BUFB     (ATILE + BTILE)        // 79872
#define GEMM_SMEM (2 * BUFB)            // 159744

template<bool BIAS, bool GELU, bool RES>
__global__ __launch_bounds__(256, 1) void tcgemm_kernel(
    const float* __restrict__ A, const float* __restrict__ B,
    const float* __restrict__ bias, const float* __restrict__ res,
    float* __restrict__ C, int M, int N, int K)
{
    extern __shared__ char smem[];
    const uint32_t sb = smem_u32(smem);
    const int tid  = threadIdx.x;
    const int lane = tid & 31;
    const int wid  = tid >> 5;
    const int wr = wid >> 2, wc = wid & 3;        // warp grid 2 x 4
    const int m0w = wr * 64, n0w = wc * 64;       // warp tile 64 x 64

    const int m0 = blockIdx.y * 128, col0 = blockIdx.x * 256;

    // ---- A loader: row = tid/2, seg = tid&1 covers 16 floats -> 96 B ----
    const int arow = tid >> 1, aseg = tid & 1;
    const int gar = m0 + arow;
    const bool aval = (gar < M);
    const float* Ap = A + (size_t)gar * K + aseg * 16;
    char* sArow = smem + arow * PITCHB + aseg * 96;

    // ---- B loader: col bn = tid, all 32 k values (strided by N) ----
    const int bn = tid;
    const float* Bp = B + col0 + bn;
    char* sBrow = smem + ATILE + bn * PITCHB;

    float dacc[32][4];
    #pragma unroll
    for (int t = 0; t < 32; t++)
        #pragma unroll
        for (int c = 0; c < 4; c++) dacc[t][c] = 0.f;

    const int NBLK = K >> 5;

    // ---- pack helpers: one A pair (p=0..7) / one B pair (j=0..15) ----
    auto packA_pair = [&](int bufo, const float4 a4[4], int p) {
        const int q = p >> 1, pp = p & 1;
        const float* vq = reinterpret_cast<const float*>(&a4[q]);
        const float v0 = vq[pp * 2], v1 = vq[pp * 2 + 1];
        const uint32_t h01 = cvt_bf16x2(v1, v0);       // [h0 | h1<<16]
        const float f0h = __uint_as_float(h01 << 16);
        const float f1h = __uint_as_float(h01 & 0xFFFF0000u);
        const uint32_t l01 = cvt_bf16x2(v1 - f1h, v0 - f0h);
        uint32_t* w = reinterpret_cast<uint32_t*>(sArow + bufo + p * 12);
        w[0] = __byte_perm(h01, h01, 0x1010);          // h0 | h0<<16
        w[1] = __byte_perm(l01, h01, 0x7610);          // l0 | h1<<16
        w[2] = __byte_perm(l01, h01, 0x3276);          // h1 | l1<<16
    };
    auto packB_pair = [&](int bufo, const float bl[32], int j) {
        const float v0 = bl[2 * j], v1 = bl[2 * j + 1];
        const uint32_t h01 = cvt_bf16x2(v1, v0);
        const float f0h = __uint_as_float(h01 << 16);
        const float f1h = __uint_as_float(h01 & 0xFFFF0000u);
        const uint32_t l01 = cvt_bf16x2(v1 - f1h, v0 - f0h);
        uint32_t* w = reinterpret_cast<uint32_t*>(sBrow + bufo + j * 12);
        w[0] = __byte_perm(l01, h01, 0x1054);          // h0 | l0<<16
        w[1] = h01;                                     // h0 | h1<<16
        w[2] = __byte_perm(l01, h01, 0x7632);          // l1 | h1<<16
    };

    // ---- preload block 0 ----
    {
        float4 a4[4]; float bl[32];
        #pragma unroll
        for (int q = 0; q < 4; q++)
            a4[q] = aval ? *reinterpret_cast<const float4*>(Ap + q * 4)
                         : make_float4(0.f, 0.f, 0.f, 0.f);
        #pragma unroll
        for (int i = 0; i < 32; i++) bl[i] = Bp[(size_t)i * N];
        #pragma unroll
        for (int p = 0; p < 8; p++) packA_pair(0, a4, p);
        #pragma unroll
        for (int j = 0; j < 16; j++) packB_pair(0, bl, j);
    }
    __syncthreads();

    int buf = 0;
    for (int blk = 0; blk < NBLK; blk++) {
        // prefetch next block into registers
        float4 a4[4]; float bl[32];
        const bool more = (blk + 1 < NBLK);
        if (more) {
            const float* Apn = Ap + (blk + 1) * 32;
            const float* Bpn = Bp + (size_t)(blk + 1) * 32 * N;
            #pragma unroll
            for (int q = 0; q < 4; q++)
                a4[q] = aval ? *reinterpret_cast<const float4*>(Apn + q * 4)
                             : make_float4(0.f, 0.f, 0.f, 0.f);
            #pragma unroll
            for (int i = 0; i < 32; i++) bl[i] = Bpn[(size_t)i * N];
        }

        // ---- compute on buffer `buf`: 6 chunks; pack next block in kc>=2 ----
        const uint32_t sA  = sb + buf * BUFB;
        const uint32_t sBB = sA + ATILE;
        const int bo = (buf ^ 1) * BUFB;
        const uint32_t aAddrBase = sA + (uint32_t)(m0w + (lane & 15)) * PITCHB
                                      + ((lane >> 4) * 8) * 2;
        const int g = lane >> 3;
        const uint32_t bAddrBase = sBB + (uint32_t)(n0w + ((g >> 1) * 8) + (lane & 7)) * PITCHB
                                       + ((g & 1) * 8) * 2;
        #pragma unroll
        for (int kc = 0; kc < 6; kc++) {
            uint32_t af[4][4], bfr[8][2];
            #pragma unroll
            for (int mi = 0; mi < 4; mi++)
                LDSM4(af[mi][0], af[mi][1], af[mi][2], af[mi][3],
                      aAddrBase + (uint32_t)mi * 16 * PITCHB + kc * 32);
            #pragma unroll
            for (int p = 0; p < 4; p++)
                LDSM4(bfr[2*p][0], bfr[2*p][1], bfr[2*p+1][0], bfr[2*p+1][1],
                      bAddrBase + (uint32_t)p * 16 * PITCHB + kc * 32);
            #pragma unroll
            for (int mi = 0; mi < 4; mi++)
                #pragma unroll
                for (int nt = 0; nt < 8; nt++)
                    MMA_BF16(dacc[mi * 8 + nt], af[mi], bfr[nt]);

            // interleaved pack of the NEXT k-block into the idle buffer
            if (kc >= 2 && more) {
                const int s = kc - 2;                    // 0..3
                packA_pair(bo, a4, 2 * s);
                packA_pair(bo, a4, 2 * s + 1);
                #pragma unroll
                for (int jj = 0; jj < 4; jj++)
                    packB_pair(bo, bl, 4 * s + jj);
            }
        }

        if (more) {
            __syncthreads();
            buf ^= 1;
        }
    }

    // ---- epilogue ----
    #pragma unroll
    for (int mi = 0; mi < 4; mi++) {
        const int r0 = m0 + m0w + mi * 16 + (lane >> 2);
        #pragma unroll
        for (int nt = 0; nt < 8; nt++) {
            const int c = col0 + n0w + nt * 8 + (lane & 3) * 2;
            const float* d = dacc[mi * 8 + nt];
            float b0 = 0.f, b1 = 0.f;
            if (BIAS) { b0 = bias[c]; b1 = bias[c + 1]; }
            #pragma unroll
            for (int half = 0; half < 2; half++) {
                const int r = r0 + half * 8;
                if (r >= M) continue;
                float v0 = d[half * 2 + 0] + b0;
                float v1 = d[half * 2 + 1] + b1;
                if (GELU) {
                    v0 = 0.5f * v0 * (1.0f + erff(v0 * 0.70710678118654752f));
                    v1 = 0.5f * v1 * (1.0f + erff(v1 * 0.70710678118654752f));
                }
                if (RES) {
                    const float2 rv = *reinterpret_cast<const float2*>(
                        res + (size_t)r * N + c);
                    v0 += rv.x; v1 += rv.y;
                }
                *reinterpret_cast<float2*>(C + (size_t)r * N + c) =
                    make_float2(v0, v1);
            }
        }
    }
}

// ---------------- LayerNorm: one block per token, 768 = 256*3 ----------------
__global__ __launch_bounds__(256) void ln_kernel(
    const float* __restrict__ x, const float* __restrict__ g,
    const float* __restrict__ b, float* __restrict__ out)
{
    const size_t t = blockIdx.x;
    const float* xr = x + t * DIM;
    const int tid = threadIdx.x;

    float v0 = xr[tid], v1 = xr[tid + 256], v2 = xr[tid + 512];
    float s  = v0 + v1 + v2;
    float ss = v0*v0 + v1*v1 + v2*v2;

    __shared__ float red[16];
    __shared__ float stat[2];
    #pragma unroll
    for (int o = 16; o; o >>= 1) {
        s  += __shfl_xor_sync(0xffffffffu, s,  o);
        ss += __shfl_xor_sync(0xffffffffu, ss, o);
    }
    if ((tid & 31) == 0) { red[tid >> 5] = s; red[(tid >> 5) + 8] = ss; }
    __syncthreads();
    if (tid == 0) {
        float a = 0.f, c = 0.f;
        #pragma unroll
        for (int i = 0; i < 8; i++) { a += red[i]; c += red[i + 8]; }
        float mu = a * (1.0f / DIM);
        float var = c * (1.0f / DIM) - mu * mu;
        stat[0] = mu;
        stat[1] = rsqrtf(var + 1e-5f);
    }
    __syncthreads();
    const float mu = stat[0], inv = stat[1];
    float* orow = out + t * DIM;
    orow[tid      ] = (v0 - mu) * inv * g[tid      ] + b[tid      ];
    orow[tid + 256] = (v1 - mu) * inv * g[tid + 256] + b[tid + 256];
    orow[tid + 512] = (v2 - mu) * inv * g[tid + 512] + b[tid + 512];
}

// ---------------- Fused flash attention (SIMT, R5-proven) ----------------
#define FA_SMEM (3 * 64 * 68 * 4)

__global__ __launch_bounds__(256) void fattn_kernel(
    const float* __restrict__ qkv, float* __restrict__ O)
{
    extern __shared__ float sm[];
    float (*Qs)[68] = reinterpret_cast<float(*)[68]>(sm);
    float (*KP)[68] = reinterpret_cast<float(*)[68]>(sm + 64 * 68);
    float (*Vs)[68] = reinterpret_cast<float(*)[68]>(sm + 2 * 64 * 68);

    const int bh = blockIdx.y;
    const int b = bh / HEADS, h = bh % HEADS;
    const int n0 = blockIdx.x * 64;
    const float* qb = qkv + (size_t)b * SEQ * QKVD + h * HD;
    const float* kb = qb + DIM;
    const float* vb = qb + 2 * DIM;

    const int tid = threadIdx.x;
    const int lr = tid >> 2;
    const int lc = (tid & 3) * 16;
    const int tx = tid & 15, ty = tid >> 4;

    {
        const int n = n0 + lr;
        const float4* src = (n < SEQ)
            ? reinterpret_cast<const float4*>(qb + (size_t)n * QKVD + lc) : nullptr;
        #pragma unroll
        for (int c4 = 0; c4 < 4; c4++) {
            float4 v = src ? src[c4] : make_float4(0.f,0.f,0.f,0.f);
            const int d = lc + c4 * 4;
            Qs[d][lr]=v.x; Qs[d+1][lr]=v.y; Qs[d+2][lr]=v.z; Qs[d+3][lr]=v.w;
        }
    }

    float acc_o[4][4];
    float row_m[4], row_l[4];
    #pragma unroll
    for (int i = 0; i < 4; i++) {
        row_m[i] = -1e30f; row_l[i] = 0.f;
        #pragma unroll
        for (int j = 0; j < 4; j++) acc_o[i][j] = 0.f;
    }

    for (int k0 = 0; k0 < SEQ; k0 += 64) {
        __syncthreads();
        {
            const int m = k0 + lr;
            const float4* srck = (m < SEQ)
                ? reinterpret_cast<const float4*>(kb + (size_t)m * QKVD + lc) : nullptr;
            const float4* srcv = (m < SEQ)
                ? reinterpret_cast<const float4*>(vb + (size_t)m * QKVD + lc) : nullptr;
            #pragma unroll
            for (int c4 = 0; c4 < 4; c4++) {
                float4 v = srck ? srck[c4] : make_float4(0.f,0.f,0.f,0.f);
                const int d = lc + c4 * 4;
                KP[d][lr]=v.x; KP[d+1][lr]=v.y; KP[d+2][lr]=v.z; KP[d+3][lr]=v.w;
                float4 w = srcv ? srcv[c4] : make_float4(0.f,0.f,0.f,0.f);
                *reinterpret_cast<float4*>(&Vs[lr][lc + c4 * 4]) = w;
            }
        }
        __syncthreads();

        float s[4][4];
        #pragma unroll
        for (int i = 0; i < 4; i++)
            #pragma unroll
            for (int j = 0; j < 4; j++) s[i][j] = 0.f;

        #pragma unroll 8
        for (int d = 0; d < 64; d++) {
            float4 ra = *reinterpret_cast<const float4*>(&Qs[d][ty * 4]);
            float4 rb = *reinterpret_cast<const float4*>(&KP[d][tx * 4]);
            float a[4] = {ra.x, ra.y, ra.z, ra.w};
            float bb[4] = {rb.x, rb.y, rb.z, rb.w};
            #pragma unroll
            for (int i = 0; i < 4; i++)
                #pragma unroll
                for (int j = 0; j < 4; j++)
                    s[i][j] = fmaf(a[i], bb[j], s[i][j]);
        }

        #pragma unroll
        for (int i = 0; i < 4; i++)
            #pragma unroll
            for (int j = 0; j < 4; j++) {
                s[i][j] *= 0.125f;
                if (k0 + tx * 4 + j >= SEQ) s[i][j] = -1e30f;
            }

        float f[4];
        #pragma unroll
        for (int i = 0; i < 4; i++) {
            float mt = fmaxf(fmaxf(s[i][0], s[i][1]), fmaxf(s[i][2], s[i][3]));
            #pragma unroll
            for (int o = 1; o < 16; o <<= 1)
                mt = fmaxf(mt, __shfl_xor_sync(0xffffffffu, mt, o, 16));
            const float nm = fmaxf(row_m[i], mt);
            f[i] = __expf(row_m[i] - nm);
            row_m[i] = nm;
            float rs = 0.f;
            #pragma unroll
            for (int j = 0; j < 4; j++) {
                s[i][j] = __expf(s[i][j] - nm);
                rs += s[i][j];
            }
            #pragma unroll
            for (int o = 1; o < 16; o <<= 1)
                rs += __shfl_xor_sync(0xffffffffu, rs, o, 16);
            row_l[i] = row_l[i] * f[i] + rs;
            #pragma unroll
            for (int j = 0; j < 4; j++) acc_o[i][j] *= f[i];
        }

        __syncthreads();
        #pragma unroll
        for (int i = 0; i < 4; i++)
            *reinterpret_cast<float4*>(&KP[ty * 4 + i][tx * 4]) =
                make_float4(s[i][0], s[i][1], s[i][2], s[i][3]);
        __syncthreads();

        #pragma unroll 4
        for (int k = 0; k < 64; k += 4) {
            float4 pa[4], vv[4];
            #pragma unroll
            for (int i = 0; i < 4; i++)
                pa[i] = *reinterpret_cast<const float4*>(&KP[ty * 4 + i][k]);
            #pragma unroll
            for (int kk = 0; kk < 4; kk++)
                vv[kk] = *reinterpret_cast<const float4*>(&Vs[k + kk][tx * 4]);
            #pragma unroll
            for (int i = 0; i < 4; i++) {
                float p[4] = {pa[i].x, pa[i].y, pa[i].z, pa[i].w};
                #pragma unroll
                for (int kk = 0; kk < 4; kk++) {
                    acc_o[i][0] = fmaf(p[kk], vv[kk].x, acc_o[i][0]);
                    acc_o[i][1] = fmaf(p[kk], vv[kk].y, acc_o[i][1]);
                    acc_o[i][2] = fmaf(p[kk], vv[kk].z, acc_o[i][2]);
                    acc_o[i][3] = fmaf(p[kk], vv[kk].w, acc_o[i][3]);
                }
            }
        }
    }

    #pragma unroll
    for (int i = 0; i < 4; i++) {
        const int n = n0 + ty * 4 + i;
        if (n >= SEQ) continue;
        const float inv = 1.0f / row_l[i];
        float4 r = make_float4(acc_o[i][0]*inv, acc_o[i][1]*inv,
                               acc_o[i][2]*inv, acc_o[i][3]*inv);
        *reinterpret_cast<float4*>(
            O + ((size_t)(b * SEQ + n)) * DIM + h * HD + tx * 4) = r;
    }
}

// ---------------- launch ----------------
extern "C" void kernel_launch(void* const* d_in, const int* in_sizes, int n_in,
                              void* d_out, int out_size)
{
    const float* x     = (const float*)d_in[0];
    const float* ln1_g = (const float*)d_in[1];
    const float* ln1_b = (const float*)d_in[2];
    const float* Wqkv  = (const float*)d_in[3];
    const float* Wproj = (const float*)d_in[4];
    const float* bproj = (const float*)d_in[5];
    const float* ln2_g = (const float*)d_in[6];
    const float* ln2_b = (const float*)d_in[7];
    const float* W1    = (const float*)d_in[8];
    const float* b1    = (const float*)d_in[9];
    const float* W2    = (const float*)d_in[10];
    const float* b2    = (const float*)d_in[11];
    float* out = (float*)d_out;

    void* p_arena;
    cudaGetSymbolAddress(&p_arena, g_arena);
    float* arena = (float*)p_arena;
    float* h_buf = arena;                               // NTOK*DIM
    float* x2buf = arena + (size_t)NTOK * DIM;          // NTOK*DIM
    float* qkvb  = arena + (size_t)NTOK * DIM * 2;      // NTOK*QKVD (overlaid)
    float* mbuf  = qkvb;                                // NTOK*HIDDEN (overlaid)

    cudaFuncSetAttribute(fattn_kernel,
                         cudaFuncAttributeMaxDynamicSharedMemorySize, FA_SMEM);
    cudaFuncSetAttribute(tcgemm_kernel<false,false,false>,
                         cudaFuncAttributeMaxDynamicSharedMemorySize, GEMM_SMEM);
    cudaFuncSetAttribute(tcgemm_kernel<true,false,true>,
                         cudaFuncAttributeMaxDynamicSharedMemorySize, GEMM_SMEM);
    cudaFuncSetAttribute(tcgemm_kernel<true,true,false>,
                         cudaFuncAttributeMaxDynamicSharedMemorySize, GEMM_SMEM);

    const int MT = (NTOK + 127) / 128;  // 289

    // 1. h = LN1(x)
    ln_kernel<<<NTOK, 256>>>(x, ln1_g, ln1_b, h_buf);
    // 2. qkv = h @ Wqkv
    tcgemm_kernel<false,false,false><<<dim3(QKVD/256, MT), 256, GEMM_SMEM>>>(
        h_buf, Wqkv, nullptr, nullptr, qkvb, NTOK, QKVD, DIM);
    // 3. fused attention -> h_buf (reused; qkv dead afterwards)
    fattn_kernel<<<dim3(10, BATCH*HEADS), 256, FA_SMEM>>>(qkvb, h_buf);
    // 4. x2 = x + O @ Wproj + bproj
    tcgemm_kernel<true,false,true><<<dim3(DIM/256, MT), 256, GEMM_SMEM>>>(
        h_buf, Wproj, bproj, x, x2buf, NTOK, DIM, DIM);
    // 5. h = LN2(x2)
    ln_kernel<<<NTOK, 256>>>(x2buf, ln2_g, ln2_b, h_buf);
    // 6. m = gelu(h @ W1 + b1)
    tcgemm_kernel<true,true,false><<<dim3(HIDDEN/256, MT), 256, GEMM_SMEM>>>(
        h_buf, W1, b1, nullptr, mbuf, NTOK, HIDDEN, DIM);
    // 7. out = x2 + m @ W2 + b2
    tcgemm_kernel<true,false,true><<<dim3(DIM/256, MT), 256, GEMM_SMEM>>>(
        mbuf, W2, b2, x2buf, out, NTOK, DIM, HIDDEN);
}